// round 16
// baseline (speedup 1.0000x reference)
#include <cuda_runtime.h>
#include <cstdint>

// ============================================================================
// CamPoseNet: Bingham ACG rejection sampler, JAX threefry-partitionable
// faithful. R14: phase-split tail compression.
//   Main phase: exact R8/R9 hot loop (no warp sync), + cheap pool-empty
//   check on the reject path (plain smem read).
//   Drain phase (cold, once per warp): adaptive cooperative speculation —
//   G = 1/2/4/8 lanes per straggler row evaluate trials t..t+G-1; lowest
//   accepting lane (= lowest t) wins, bit-identical to sequential accept.
// ============================================================================

#define T_MAX   160
#define NROWS   1048576
#define GRID    888                       // 148 SMs x 6 CTAs, all resident
#define NSAMP   (GRID - 1)                // block 0 = chain producer
#define CHUNK   ((NROWS + NSAMP - 1) / NSAMP)   // 1183

#define LAM0  1e-06f
#define SA0   (1.0f + 2e-06f)

__device__ uint4    g_keys[T_MAX];        // (k1.hi, k1.lo, k2.hi, k2.lo)
__device__ uint32_t g_progress;           // #keys published (monotonic)

// ---------------------------------------------------------------------------
// threefry2x32, exactly as jax/_src/prng.py (20 rounds, 5 key injections)
// ---------------------------------------------------------------------------
__device__ __forceinline__ void tf2x32(uint32_t k0, uint32_t k1,
                                       uint32_t x0, uint32_t x1,
                                       uint32_t &o0, uint32_t &o1) {
  uint32_t k2 = k0 ^ k1 ^ 0x1BD11BDAu;
  x0 += k0; x1 += k1;
#define TF_RND(r) { x0 += x1; x1 = __funnelshift_l(x1, x1, (r)); x1 ^= x0; }
  TF_RND(13) TF_RND(15) TF_RND(26) TF_RND(6)
  x0 += k1; x1 += k2 + 1u;
  TF_RND(17) TF_RND(29) TF_RND(16) TF_RND(24)
  x0 += k2; x1 += k0 + 2u;
  TF_RND(13) TF_RND(15) TF_RND(26) TF_RND(6)
  x0 += k0; x1 += k1 + 3u;
  TF_RND(17) TF_RND(29) TF_RND(16) TF_RND(24)
  x0 += k1; x1 += k2 + 4u;
  TF_RND(13) TF_RND(15) TF_RND(26) TF_RND(6)
  x0 += k2; x1 += k0 + 5u;
#undef TF_RND
  o0 = x0; o1 = x1;
}

__device__ __forceinline__ uint32_t ld_acq(uint32_t* p) {
  uint32_t v;
  asm volatile("ld.acquire.gpu.b32 %0, [%1];" : "=r"(v) : "l"(p) : "memory");
  return v;
}

__device__ __forceinline__ uint32_t wait_key(uint32_t seen, int t) {
  if ((int)seen > t) return seen;
  seen = ld_acq(&g_progress);
  while ((int)seen <= t) { __nanosleep(64); seen = ld_acq(&g_progress); }
  return seen;
}

// ---------------------------------------------------------------------------
// XLA ErfInv32 (Giles), separately-rounded mul/add (XLA does not fuse).
// ---------------------------------------------------------------------------
__device__ __forceinline__ float erfinv_xla(float x) {
  float xx = __fmul_rn(x, x);
  float w  = -log1pf(-xx);
  float p;
  if (w < 5.0f) {
    float wl = __fadd_rn(w, -2.5f);
    p = 2.81022636e-08f;
    p = __fadd_rn(__fmul_rn(p, wl),  3.43273939e-07f);
    p = __fadd_rn(__fmul_rn(p, wl), -3.5233877e-06f);
    p = __fadd_rn(__fmul_rn(p, wl), -4.39150654e-06f);
    p = __fadd_rn(__fmul_rn(p, wl),  0.00021858087f);
    p = __fadd_rn(__fmul_rn(p, wl), -0.00125372503f);
    p = __fadd_rn(__fmul_rn(p, wl), -0.00417768164f);
    p = __fadd_rn(__fmul_rn(p, wl),  0.246640727f);
    p = __fadd_rn(__fmul_rn(p, wl),  1.50140941f);
  } else {
    float wg = __fadd_rn(__fsqrt_rn(w), -3.0f);
    p = -0.000200214257f;
    p = __fadd_rn(__fmul_rn(p, wg),  0.000100950558f);
    p = __fadd_rn(__fmul_rn(p, wg),  0.00134934322f);
    p = __fadd_rn(__fmul_rn(p, wg), -0.00367342844f);
    p = __fadd_rn(__fmul_rn(p, wg),  0.00573950773f);
    p = __fadd_rn(__fmul_rn(p, wg), -0.0076224613f);
    p = __fadd_rn(__fmul_rn(p, wg),  0.00943887047f);
    p = __fadd_rn(__fmul_rn(p, wg),  1.00167406f);
    p = __fadd_rn(__fmul_rn(p, wg),  2.83297682f);
  }
  return __fmul_rn(p, x);
}

__device__ __forceinline__ float bits_to_unit(uint32_t b) {
  return __fadd_rn(__uint_as_float((b >> 9) | 0x3F800000u), -1.0f);
}

// ---------------------------------------------------------------------------
// One ACG trial, bit-faithful to the reference decision path.
// ---------------------------------------------------------------------------
__device__ __forceinline__ bool trial(const uint32_t bits[4], uint32_t ub,
                                      const float lam[3], const float sig[3],
                                      const float sa[3], float sig0,
                                      float X[4]) {
  float yp[4];
#pragma unroll
  for (int j = 0; j < 4; ++j) {
    float f  = bits_to_unit(bits[j]);
    float un = __fadd_rn(__fmul_rn(f, 2.0f), -0.99999994f);
    float e  = erfinv_xla(un);
    float nr = __fmul_rn(1.41421356f, e);
    yp[j]    = __fmul_rn(nr, (j == 0) ? sig0 : sig[j - 1]);
  }
  float s = __fmul_rn(yp[0], yp[0]);
  s = __fadd_rn(s, __fmul_rn(yp[1], yp[1]));
  s = __fadd_rn(s, __fmul_rn(yp[2], yp[2]));
  s = __fadd_rn(s, __fmul_rn(yp[3], yp[3]));
  float nrm = __fsqrt_rn(s);
  float cy[4], y2[4];
#pragma unroll
  for (int j = 0; j < 4; ++j) {
    cy[j] = __fdiv_rn(yp[j], nrm);
    y2[j] = __fmul_rn(cy[j], cy[j]);
  }
  float s1 = __fmul_rn(y2[0], LAM0);
  s1 = __fadd_rn(s1, __fmul_rn(y2[1], lam[0]));
  s1 = __fadd_rn(s1, __fmul_rn(y2[2], lam[1]));
  s1 = __fadd_rn(s1, __fmul_rn(y2[3], lam[2]));
  float s2 = __fmul_rn(y2[0], SA0);
  s2 = __fadd_rn(s2, __fmul_rn(y2[1], sa[0]));
  s2 = __fadd_rn(s2, __fmul_rn(y2[2], sa[1]));
  s2 = __fadd_rn(s2, __fmul_rn(y2[3], sa[2]));
  float lr = __fadd_rn(-s1, -2.7725887f);
  lr = __fadd_rn(lr, 1.5f);
  lr = __fadd_rn(lr, __fmul_rn(2.0f, logf(s2)));
  float uf = bits_to_unit(ub);
  bool acc = (logf(uf) < lr);
  if (acc) { X[0] = cy[0]; X[1] = cy[1]; X[2] = cy[2]; X[3] = cy[3]; }
  return acc;
}

__device__ __forceinline__ void gen_bits(uint4 kk, int row,
                                         uint32_t bits[4], uint32_t &ub) {
  uint32_t base = 4u * (uint32_t)row;
#pragma unroll
  for (int j = 0; j < 4; ++j) {
    uint32_t a, b;
    tf2x32(kk.x, kk.y, 0u, base + (uint32_t)j, a, b);
    bits[j] = a ^ b;
  }
  uint32_t u0, u1;
  tf2x32(kk.z, kk.w, 0u, (uint32_t)row, u0, u1);
  ub = u0 ^ u1;
}

// ---------------------------------------------------------------------------
// Epilogue: qn = q/||q||; out_j = sum_i E[i][j] * X[i]
// ---------------------------------------------------------------------------
__device__ __forceinline__ void write_out(const float4* __restrict__ q4,
                                          float4* __restrict__ out4,
                                          int row, const float X[4]) {
  float4 qv = q4[row];
  float s = __fmul_rn(qv.x, qv.x);
  s = __fmaf_rn(qv.y, qv.y, s);
  s = __fmaf_rn(qv.z, qv.z, s);
  s = __fmaf_rn(qv.w, qv.w, s);
  float n  = __fsqrt_rn(s);
  float q0 = __fdiv_rn(qv.x, n), q1 = __fdiv_rn(qv.y, n);
  float q2 = __fdiv_rn(qv.z, n), q3 = __fdiv_rn(qv.w, n);
  float o0 = __fmul_rn(q0, X[0]);
  o0 = __fmaf_rn(q1, X[1], o0); o0 = __fmaf_rn(q2, X[2], o0); o0 = __fmaf_rn(q3, X[3], o0);
  float o1 = __fmul_rn(-q1, X[0]);
  o1 = __fmaf_rn(q0, X[1], o1); o1 = __fmaf_rn(-q3, X[2], o1); o1 = __fmaf_rn(q2, X[3], o1);
  float o2 = __fmul_rn(-q2, X[0]);
  o2 = __fmaf_rn(q3, X[1], o2); o2 = __fmaf_rn(q0, X[2], o2); o2 = __fmaf_rn(-q1, X[3], o2);
  float o3 = __fmul_rn(q3, X[0]);
  o3 = __fmaf_rn(q2, X[1], o3); o3 = __fmaf_rn(-q1, X[2], o3); o3 = __fmaf_rn(-q0, X[3], o3);
  out4[row] = make_float4(o0, o1, o2, o3);
}

// ---------------------------------------------------------------------------
// Fused kernel. Block 0: chain producer. Others: R8-style compacted main
// loop, then cooperative drain once the pool is empty.
// ---------------------------------------------------------------------------
__global__ __launch_bounds__(256, 6)
void fused_kernel(const float* __restrict__ q, const float* __restrict__ Z,
                  float* __restrict__ out, const int* __restrict__ seed_ptr) {
  __shared__ int s_ctr;

  if (blockIdx.x == 0) {
    if (threadIdx.x == 0) {
      uint32_t c0 = 0u;
      uint32_t c1 = (uint32_t)(*seed_ptr);   // jax.random.key(seed) = (0,seed)
      for (int t = 0; t < T_MAX; ++t) {
        uint32_t k1a, k1b, k2a, k2b, n0, n1;
        tf2x32(c0, c1, 0u, 1u, k1a, k1b);
        tf2x32(c0, c1, 0u, 2u, k2a, k2b);
        tf2x32(c0, c1, 0u, 0u, n0, n1);
        g_keys[t] = make_uint4(k1a, k1b, k2a, k2b);
        __threadfence();                           // release g_keys[t]
        atomicMax(&g_progress, (uint32_t)(t + 1)); // monotonic across replays
        c0 = n0; c1 = n1;
      }
    }
    return;
  }

  int c         = (int)blockIdx.x - 1;
  int row_start = c * CHUNK;
  int row_end   = min(row_start + CHUNK, NROWS);
  if (threadIdx.x == 0) s_ctr = row_start;
  __syncthreads();

  const float4* q4 = reinterpret_cast<const float4*>(q);
  float4*       o4 = reinterpret_cast<float4*>(out);
  const float SIG0 = __fsqrt_rn(__fdiv_rn(1.0f, SA0));
  const unsigned FULL = 0xFFFFFFFFu;
  int lane = threadIdx.x & 31;

  float lam[3], sig[3], sa[3], X[4];
  auto load_row = [&](int r, float* lm, float* sg, float* sA) {
    lm[0] = -Z[3 * r + 0];
    lm[1] = -Z[3 * r + 1];
    lm[2] = -Z[3 * r + 2];
#pragma unroll
    for (int j = 0; j < 3; ++j) {
      sA[j] = __fadd_rn(__fmul_rn(2.0f, lm[j]), 1.0f);
      sg[j] = __fsqrt_rn(__fdiv_rn(1.0f, sA[j]));
    }
  };

  int row = atomicAdd(&s_ctr, 1);
  bool act = (row < row_end);
  if (act) { load_row(row, lam, sig, sa); X[0]=X[1]=X[2]=X[3]=0.f; }
  int t = 0;
  uint32_t seen = 0;
  volatile int* vctr = &s_ctr;

  // ===== main phase: R8 hot loop (no warp sync) =====
  while (act) {
    seen = wait_key(seen, t);
    uint32_t bits[4], ub;
    gen_bits(g_keys[t], row, bits, ub);
    bool acc = trial(bits, ub, lam, sig, sa, SIG0, X);
    if (acc || t == T_MAX - 1) {
      write_out(q4, o4, row, X);
      int nr = atomicAdd(&s_ctr, 1);
      if (nr < row_end) {
        row = nr; load_row(row, lam, sig, sa);
        X[0]=X[1]=X[2]=X[3]=0.f;
        t = 0;
      } else { act = false; }          // pool empty, row finished
    } else {
      ++t;
      if (*vctr >= row_end) break;     // pool empty, row IN FLIGHT -> drain
    }
  }

  // ===== drain phase: adaptive cooperative speculation =====
  for (;;) {
    unsigned m = __ballot_sync(FULL, act);
    if (!m) break;
    int na = __popc(m);
    int G  = (na > 16) ? 1 : (na > 8) ? 2 : (na > 4) ? 4 : 8;  // lanes/row

    if (G == 1) {
      // still many stragglers: per-lane trials (no pulls; pool is empty)
      if (act) {
        seen = wait_key(seen, t);
        uint32_t bits[4], ub;
        gen_bits(g_keys[t], row, bits, ub);
        bool acc = trial(bits, ub, lam, sig, sa, SIG0, X);
        if (acc || t == T_MAX - 1) { write_out(q4, o4, row, X); act = false; }
        else ++t;
      }
    } else {
      int g    = lane / G;                         // my helper group
      bool have = (g < na);
      int src   = have ? (int)__fns(m, 0, g + 1) : 0;
      int row_s = __shfl_sync(FULL, row, src);
      int t_s   = __shfl_sync(FULL, t,   src);
      int my_t  = t_s + (lane % G);
      bool acc  = false;
      float Xl[4] = {0.f, 0.f, 0.f, 0.f};
      if (have && my_t < T_MAX) {
        seen = wait_key(seen, my_t);
        float lamL[3], sigL[3], saL[3];
        load_row(row_s, lamL, sigL, saL);
        uint32_t bits[4], ub;
        gen_bits(g_keys[my_t], row_s, bits, ub);
        acc = trial(bits, ub, lamL, sigL, saL, SIG0, Xl);
        if (my_t == T_MAX - 1) acc = true;         // forced (unreachable)
      }
      unsigned am   = __ballot_sync(FULL, acc);
      unsigned gmask = ((G == 32 ? 0xFFFFFFFFu : ((1u << G) - 1u)) << (g * G));
      unsigned gacc = am & gmask;
      if (have && gacc) {
        int winner = __ffs(gacc) - 1;              // lowest lane = lowest t
        if (lane == winner) write_out(q4, o4, row_s, Xl);
      }
      if (act) {                                   // straggler updates state
        int myrank = __popc(m & ((1u << lane) - 1u));
        unsigned mymask = ((1u << G) - 1u) << (myrank * G);
        if (am & mymask) act = false;              // my row got accepted
        else t += G;
      }
    }
  }
}

// ---------------------------------------------------------------------------
extern "C" void kernel_launch(void* const* d_in, const int* in_sizes, int n_in,
                              void* d_out, int out_size) {
  const float* q    = (const float*)d_in[0];
  const float* Z    = (const float*)d_in[1];
  const int*   seed = (const int*)d_in[2];
  float* out = (float*)d_out;
  fused_kernel<<<GRID, 256>>>(q, Z, out, seed);
}

// round 17
// speedup vs baseline: 1.3759x; 1.3759x over previous
#include <cuda_runtime.h>
#include <cstdint>

// ============================================================================
// CamPoseNet: Bingham ACG rejection sampler, JAX threefry-partitionable
// faithful. R16: phase-split tail compression, drain made memory-free.
//   Main phase: R8 hot loop (no warp sync), cheap pool-empty check on the
//   reject path (plain smem read).
//   Drain phase (cold): adaptive cooperative speculation, G = 1/2/4/8 lanes
//   per straggler row evaluating trials t..t+G-1; owner params distributed
//   via register shuffles (NO gmem reloads). Lowest accepting lane wins
//   (= lowest t) — bit-identical to the sequential first-accept.
// ============================================================================

#define T_MAX   160
#define NROWS   1048576
#define GRID    888                       // 148 SMs x 6 CTAs, all resident
#define NSAMP   (GRID - 1)                // block 0 = chain producer
#define CHUNK   ((NROWS + NSAMP - 1) / NSAMP)   // 1183

#define LAM0  1e-06f
#define SA0   (1.0f + 2e-06f)

__device__ uint4    g_keys[T_MAX];        // (k1.hi, k1.lo, k2.hi, k2.lo)
__device__ uint32_t g_progress;           // #keys published (monotonic)

// ---------------------------------------------------------------------------
// threefry2x32, exactly as jax/_src/prng.py (20 rounds, 5 key injections)
// ---------------------------------------------------------------------------
__device__ __forceinline__ void tf2x32(uint32_t k0, uint32_t k1,
                                       uint32_t x0, uint32_t x1,
                                       uint32_t &o0, uint32_t &o1) {
  uint32_t k2 = k0 ^ k1 ^ 0x1BD11BDAu;
  x0 += k0; x1 += k1;
#define TF_RND(r) { x0 += x1; x1 = __funnelshift_l(x1, x1, (r)); x1 ^= x0; }
  TF_RND(13) TF_RND(15) TF_RND(26) TF_RND(6)
  x0 += k1; x1 += k2 + 1u;
  TF_RND(17) TF_RND(29) TF_RND(16) TF_RND(24)
  x0 += k2; x1 += k0 + 2u;
  TF_RND(13) TF_RND(15) TF_RND(26) TF_RND(6)
  x0 += k0; x1 += k1 + 3u;
  TF_RND(17) TF_RND(29) TF_RND(16) TF_RND(24)
  x0 += k1; x1 += k2 + 4u;
  TF_RND(13) TF_RND(15) TF_RND(26) TF_RND(6)
  x0 += k2; x1 += k0 + 5u;
#undef TF_RND
  o0 = x0; o1 = x1;
}

__device__ __forceinline__ uint32_t ld_acq(uint32_t* p) {
  uint32_t v;
  asm volatile("ld.acquire.gpu.b32 %0, [%1];" : "=r"(v) : "l"(p) : "memory");
  return v;
}

__device__ __forceinline__ uint32_t wait_key(uint32_t seen, int t) {
  if ((int)seen > t) return seen;
  seen = ld_acq(&g_progress);
  while ((int)seen <= t) { __nanosleep(64); seen = ld_acq(&g_progress); }
  return seen;
}

// ---------------------------------------------------------------------------
// XLA ErfInv32 (Giles), separately-rounded mul/add (XLA does not fuse).
// ---------------------------------------------------------------------------
__device__ __forceinline__ float erfinv_xla(float x) {
  float xx = __fmul_rn(x, x);
  float w  = -log1pf(-xx);
  float p;
  if (w < 5.0f) {
    float wl = __fadd_rn(w, -2.5f);
    p = 2.81022636e-08f;
    p = __fadd_rn(__fmul_rn(p, wl),  3.43273939e-07f);
    p = __fadd_rn(__fmul_rn(p, wl), -3.5233877e-06f);
    p = __fadd_rn(__fmul_rn(p, wl), -4.39150654e-06f);
    p = __fadd_rn(__fmul_rn(p, wl),  0.00021858087f);
    p = __fadd_rn(__fmul_rn(p, wl), -0.00125372503f);
    p = __fadd_rn(__fmul_rn(p, wl), -0.00417768164f);
    p = __fadd_rn(__fmul_rn(p, wl),  0.246640727f);
    p = __fadd_rn(__fmul_rn(p, wl),  1.50140941f);
  } else {
    float wg = __fadd_rn(__fsqrt_rn(w), -3.0f);
    p = -0.000200214257f;
    p = __fadd_rn(__fmul_rn(p, wg),  0.000100950558f);
    p = __fadd_rn(__fmul_rn(p, wg),  0.00134934322f);
    p = __fadd_rn(__fmul_rn(p, wg), -0.00367342844f);
    p = __fadd_rn(__fmul_rn(p, wg),  0.00573950773f);
    p = __fadd_rn(__fmul_rn(p, wg), -0.0076224613f);
    p = __fadd_rn(__fmul_rn(p, wg),  0.00943887047f);
    p = __fadd_rn(__fmul_rn(p, wg),  1.00167406f);
    p = __fadd_rn(__fmul_rn(p, wg),  2.83297682f);
  }
  return __fmul_rn(p, x);
}

__device__ __forceinline__ float bits_to_unit(uint32_t b) {
  return __fadd_rn(__uint_as_float((b >> 9) | 0x3F800000u), -1.0f);
}

// ---------------------------------------------------------------------------
// One ACG trial, bit-faithful to the reference decision path.
// ---------------------------------------------------------------------------
__device__ __forceinline__ bool trial(const uint32_t bits[4], uint32_t ub,
                                      const float lam[3], const float sig[3],
                                      const float sa[3], float sig0,
                                      float X[4]) {
  float yp[4];
#pragma unroll
  for (int j = 0; j < 4; ++j) {
    float f  = bits_to_unit(bits[j]);
    float un = __fadd_rn(__fmul_rn(f, 2.0f), -0.99999994f);
    float e  = erfinv_xla(un);
    float nr = __fmul_rn(1.41421356f, e);
    yp[j]    = __fmul_rn(nr, (j == 0) ? sig0 : sig[j - 1]);
  }
  float s = __fmul_rn(yp[0], yp[0]);
  s = __fadd_rn(s, __fmul_rn(yp[1], yp[1]));
  s = __fadd_rn(s, __fmul_rn(yp[2], yp[2]));
  s = __fadd_rn(s, __fmul_rn(yp[3], yp[3]));
  float nrm = __fsqrt_rn(s);
  float cy[4], y2[4];
#pragma unroll
  for (int j = 0; j < 4; ++j) {
    cy[j] = __fdiv_rn(yp[j], nrm);
    y2[j] = __fmul_rn(cy[j], cy[j]);
  }
  float s1 = __fmul_rn(y2[0], LAM0);
  s1 = __fadd_rn(s1, __fmul_rn(y2[1], lam[0]));
  s1 = __fadd_rn(s1, __fmul_rn(y2[2], lam[1]));
  s1 = __fadd_rn(s1, __fmul_rn(y2[3], lam[2]));
  float s2 = __fmul_rn(y2[0], SA0);
  s2 = __fadd_rn(s2, __fmul_rn(y2[1], sa[0]));
  s2 = __fadd_rn(s2, __fmul_rn(y2[2], sa[1]));
  s2 = __fadd_rn(s2, __fmul_rn(y2[3], sa[2]));
  float lr = __fadd_rn(-s1, -2.7725887f);
  lr = __fadd_rn(lr, 1.5f);
  lr = __fadd_rn(lr, __fmul_rn(2.0f, logf(s2)));
  float uf = bits_to_unit(ub);
  bool acc = (logf(uf) < lr);
  if (acc) { X[0] = cy[0]; X[1] = cy[1]; X[2] = cy[2]; X[3] = cy[3]; }
  return acc;
}

__device__ __forceinline__ void gen_bits(uint4 kk, int row,
                                         uint32_t bits[4], uint32_t &ub) {
  uint32_t base = 4u * (uint32_t)row;
#pragma unroll
  for (int j = 0; j < 4; ++j) {
    uint32_t a, b;
    tf2x32(kk.x, kk.y, 0u, base + (uint32_t)j, a, b);
    bits[j] = a ^ b;
  }
  uint32_t u0, u1;
  tf2x32(kk.z, kk.w, 0u, (uint32_t)row, u0, u1);
  ub = u0 ^ u1;
}

// ---------------------------------------------------------------------------
// Epilogue: qn = q/||q||; out_j = sum_i E[i][j] * X[i]
// ---------------------------------------------------------------------------
__device__ __forceinline__ void write_out(const float4* __restrict__ q4,
                                          float4* __restrict__ out4,
                                          int row, const float X[4]) {
  float4 qv = q4[row];
  float s = __fmul_rn(qv.x, qv.x);
  s = __fmaf_rn(qv.y, qv.y, s);
  s = __fmaf_rn(qv.z, qv.z, s);
  s = __fmaf_rn(qv.w, qv.w, s);
  float n  = __fsqrt_rn(s);
  float q0 = __fdiv_rn(qv.x, n), q1 = __fdiv_rn(qv.y, n);
  float q2 = __fdiv_rn(qv.z, n), q3 = __fdiv_rn(qv.w, n);
  float o0 = __fmul_rn(q0, X[0]);
  o0 = __fmaf_rn(q1, X[1], o0); o0 = __fmaf_rn(q2, X[2], o0); o0 = __fmaf_rn(q3, X[3], o0);
  float o1 = __fmul_rn(-q1, X[0]);
  o1 = __fmaf_rn(q0, X[1], o1); o1 = __fmaf_rn(-q3, X[2], o1); o1 = __fmaf_rn(q2, X[3], o1);
  float o2 = __fmul_rn(-q2, X[0]);
  o2 = __fmaf_rn(q3, X[1], o2); o2 = __fmaf_rn(q0, X[2], o2); o2 = __fmaf_rn(-q1, X[3], o2);
  float o3 = __fmul_rn(q3, X[0]);
  o3 = __fmaf_rn(q2, X[1], o3); o3 = __fmaf_rn(-q1, X[2], o3); o3 = __fmaf_rn(-q0, X[3], o3);
  out4[row] = make_float4(o0, o1, o2, o3);
}

// ---------------------------------------------------------------------------
// Fused kernel. Block 0: chain producer. Others: R8-style compacted main
// loop, then memory-free cooperative drain once the pool is empty.
// ---------------------------------------------------------------------------
__global__ __launch_bounds__(256, 6)
void fused_kernel(const float* __restrict__ q, const float* __restrict__ Z,
                  float* __restrict__ out, const int* __restrict__ seed_ptr) {
  __shared__ int s_ctr;

  if (blockIdx.x == 0) {
    if (threadIdx.x == 0) {
      uint32_t c0 = 0u;
      uint32_t c1 = (uint32_t)(*seed_ptr);   // jax.random.key(seed) = (0,seed)
      for (int t = 0; t < T_MAX; ++t) {
        uint32_t k1a, k1b, k2a, k2b, n0, n1;
        tf2x32(c0, c1, 0u, 1u, k1a, k1b);
        tf2x32(c0, c1, 0u, 2u, k2a, k2b);
        tf2x32(c0, c1, 0u, 0u, n0, n1);
        g_keys[t] = make_uint4(k1a, k1b, k2a, k2b);
        __threadfence();                           // release g_keys[t]
        atomicMax(&g_progress, (uint32_t)(t + 1)); // monotonic across replays
        c0 = n0; c1 = n1;
      }
    }
    return;
  }

  int c         = (int)blockIdx.x - 1;
  int row_start = c * CHUNK;
  int row_end   = min(row_start + CHUNK, NROWS);
  if (threadIdx.x == 0) s_ctr = row_start;
  __syncthreads();

  const float4* q4 = reinterpret_cast<const float4*>(q);
  float4*       o4 = reinterpret_cast<float4*>(out);
  const float SIG0 = __fsqrt_rn(__fdiv_rn(1.0f, SA0));
  const unsigned FULL = 0xFFFFFFFFu;
  int lane = threadIdx.x & 31;

  float lam[3], sig[3], sa[3], X[4];
  auto load_row = [&](int r) {
    lam[0] = -Z[3 * r + 0];
    lam[1] = -Z[3 * r + 1];
    lam[2] = -Z[3 * r + 2];
#pragma unroll
    for (int j = 0; j < 3; ++j) {
      sa[j]  = __fadd_rn(__fmul_rn(2.0f, lam[j]), 1.0f);
      sig[j] = __fsqrt_rn(__fdiv_rn(1.0f, sa[j]));
    }
  };

  int row = atomicAdd(&s_ctr, 1);
  bool act = (row < row_end);
  if (act) { load_row(row); X[0]=X[1]=X[2]=X[3]=0.f; }
  int t = 0;
  uint32_t seen = 0;
  volatile int* vctr = &s_ctr;

  // ===== main phase: R8 hot loop (no warp sync) =====
  while (act) {
    seen = wait_key(seen, t);
    uint32_t bits[4], ub;
    gen_bits(g_keys[t], row, bits, ub);
    bool acc = trial(bits, ub, lam, sig, sa, SIG0, X);
    if (acc || t == T_MAX - 1) {
      write_out(q4, o4, row, X);
      int nr = atomicAdd(&s_ctr, 1);
      if (nr < row_end) {
        row = nr; load_row(row);
        X[0]=X[1]=X[2]=X[3]=0.f;
        t = 0;
      } else { act = false; }          // pool empty, row finished
    } else {
      ++t;
      if (*vctr >= row_end) break;     // pool empty, row IN FLIGHT -> drain
    }
  }

  // ===== drain phase: memory-free adaptive cooperative speculation =====
  for (;;) {
    unsigned m = __ballot_sync(FULL, act);
    if (!m) break;
    int na = __popc(m);
    int G  = (na > 16) ? 1 : (na > 8) ? 2 : (na > 4) ? 4 : 8;  // lanes/row

    if (G == 1) {
      // still many stragglers: per-lane trials (no pulls; pool is empty)
      if (act) {
        seen = wait_key(seen, t);
        uint32_t bits[4], ub;
        gen_bits(g_keys[t], row, bits, ub);
        bool acc = trial(bits, ub, lam, sig, sa, SIG0, X);
        if (acc || t == T_MAX - 1) { write_out(q4, o4, row, X); act = false; }
        else ++t;
      }
    } else {
      int g     = lane / G;                        // my helper group
      bool have = (g < na);
      int src   = have ? (int)__fns(m, 0, g + 1) : 0;
      // distribute owner state by shuffle — NO gmem traffic in the drain
      int row_s = __shfl_sync(FULL, row, src);
      int t_s   = __shfl_sync(FULL, t,   src);
      float lamL[3], sigL[3], saL[3];
#pragma unroll
      for (int j = 0; j < 3; ++j) {
        lamL[j] = __shfl_sync(FULL, lam[j], src);
        sigL[j] = __shfl_sync(FULL, sig[j], src);
        saL[j]  = __shfl_sync(FULL, sa[j],  src);
      }
      int my_t  = t_s + (lane % G);
      bool acc  = false;
      float Xl[4] = {0.f, 0.f, 0.f, 0.f};
      if (have && my_t < T_MAX) {
        seen = wait_key(seen, my_t);
        uint32_t bits[4], ub;
        gen_bits(g_keys[my_t], row_s, bits, ub);
        acc = trial(bits, ub, lamL, sigL, saL, SIG0, Xl);
        if (my_t == T_MAX - 1) acc = true;         // forced (unreachable)
      }
      unsigned am    = __ballot_sync(FULL, acc);
      unsigned gmask = ((1u << G) - 1u) << (g * G);
      unsigned gacc  = am & gmask;
      if (have && gacc) {
        int winner = __ffs(gacc) - 1;              // lowest lane = lowest t
        if (lane == winner) write_out(q4, o4, row_s, Xl);
      }
      if (act) {                                   // straggler updates state
        int myrank = __popc(m & ((1u << lane) - 1u));
        unsigned mymask = ((1u << G) - 1u) << (myrank * G);
        if (am & mymask) act = false;              // my row got accepted
        else t += G;
      }
    }
  }
}

// ---------------------------------------------------------------------------
extern "C" void kernel_launch(void* const* d_in, const int* in_sizes, int n_in,
                              void* d_out, int out_size) {
  const float* q    = (const float*)d_in[0];
  const float* Z    = (const float*)d_in[1];
  const int*   seed = (const int*)d_in[2];
  float* out = (float*)d_out;
  fused_kernel<<<GRID, 256>>>(q, Z, out, seed);
}